// round 12
// baseline (speedup 1.0000x reference)
#include <cuda_runtime.h>
#include <cstdint>
#include <math.h>

#define LL 512
#define CC 128
#define NROWS (LL*LL)   // 262144

// ---- scratch ----
__device__ float g_Wt[6*CC*CC];     // tf32-rounded weights: w_l, w_lg, w_r, w_rg, w_fgate, w_out
__device__ float g_Lt[CC*NROWS];    // left  gated+masked, c-major planes, k-interleaved [0,4,1,5,2,6,3,7]/8-group
__device__ float g_Rt[CC*NROWS];    // right gated+masked, same layout
__device__ float g_Fg[NROWS*CC];    // sigmoid(final gate), n-major
__device__ float g_Ot[CC*NROWS];    // einsum output, c-major planes [c][i*512+j]

__device__ __forceinline__ float sigf(float x) {
    return 1.0f / (1.0f + __expf(-x));
}
__device__ __forceinline__ float tf32r(float x) {
    uint32_t y;
    asm("cvt.rna.tf32.f32 %0, %1;" : "=r"(y) : "f"(x));
    return __uint_as_float(y);
}
__device__ __forceinline__ void mma_tf32(float* c, const uint32_t* a, const uint32_t* b) {
    asm volatile(
        "mma.sync.aligned.m16n8k8.row.col.f32.tf32.tf32.f32 "
        "{%0,%1,%2,%3}, {%4,%5,%6,%7}, {%8,%9}, {%0,%1,%2,%3};"
        : "+f"(c[0]), "+f"(c[1]), "+f"(c[2]), "+f"(c[3])
        : "r"(a[0]), "r"(a[1]), "r"(a[2]), "r"(a[3]), "r"(b[0]), "r"(b[1]));
}
__device__ __forceinline__ void cp16(float* smem, const float* gmem) {
    uint32_t s = (uint32_t)__cvta_generic_to_shared(smem);
    asm volatile("cp.async.ca.shared.global [%0], [%1], 16;" :: "r"(s), "l"(gmem));
}

// ---------------- weight prep: tf32-round all 6 weights once ----------------
__global__ void prep_weights(const float* __restrict__ w0, const float* __restrict__ w1,
                             const float* __restrict__ w2, const float* __restrict__ w3,
                             const float* __restrict__ w4, const float* __restrict__ w5)
{
    int i = blockIdx.x * 256 + threadIdx.x;       // 0 .. 98303
    int w = i >> 14;
    int e = i & 16383;
    const float* src = (w == 0) ? w0 : (w == 1) ? w1 : (w == 2) ? w2
                     : (w == 3) ? w3 : (w == 4) ? w4 : w5;
    g_Wt[i] = tf32r(src[e]);
}

// ---------------- fused LN + projections + gates + mask (+ fgate) ----------------
// grid (5, 2048). v = blockIdx.x:
//   v 0..3: (sel = v>>1: 0=L, 1=R) x (half = v&1: 64-col slice) -> g_Lt / g_Rt (c-major, k-interleaved)
//   v 4   : fgate; acc bank = cols 0-63, accg bank = cols 64-127 -> g_Fg (n-major, sigmoid)
// Block loads its 128x128 act tile once, LN-normalizes in smem, then weight-pipelined mma.
__global__ void __launch_bounds__(256) ln_proj(
    const float* __restrict__ act,
    const float* __restrict__ nsc, const float* __restrict__ nbi,
    const float* __restrict__ b_l,  const float* __restrict__ b_lg,
    const float* __restrict__ b_r,  const float* __restrict__ b_rg,
    const float* __restrict__ b_fg,
    const float* __restrict__ mask)
{
    extern __shared__ float sm[];
    float* xt  = sm;                        // 128 x 132 (normalized tf32 X tile)
    float* ws0 = sm + 16896;                // [2][16*72]
    float* wgs0= sm + 16896 + 2304;         // [2][16*72]
    float* mu  = sm + 16896 + 4608;         // 128
    float* rs  = mu + 128;                  // 128
    float* scb = rs + 128;                  // 256: [0:128) scale, [128:256) bias

    const int v = blockIdx.x;
    const float *W, *Wg, *B, *Bg;
    float* dstT = nullptr;
    if (v < 4) {
        int sel = v >> 1, half = v & 1;
        W  = g_Wt + (sel ? 2 : 0) * CC * CC + half * 64;
        Wg = g_Wt + (sel ? 3 : 1) * CC * CC + half * 64;
        B  = (sel ? b_r  : b_l)  + half * 64;
        Bg = (sel ? b_rg : b_lg) + half * 64;
        dstT = (sel ? g_Rt : g_Lt) + (size_t)(half * 64) * NROWS;
    } else {
        W  = g_Wt + 4 * CC * CC;        // fgate cols 0-63
        Wg = g_Wt + 4 * CC * CC + 64;   // fgate cols 64-127
        B  = b_fg;
        Bg = b_fg + 64;
    }

    const int n0   = blockIdx.y * 128;
    const int tid  = threadIdx.x;
    const int wid  = tid >> 5;
    const int lane = tid & 31;
    const int warp_m = wid >> 2;
    const int warp_n = wid & 3;
    const int lr = lane >> 2;
    const int lc = lane & 3;

    // --- load act tile + LN params ---
    scb[tid] = (tid < 128) ? nsc[tid] : nbi[tid - 128];
    #pragma unroll
    for (int u = 0; u < 16; u++) {
        int idx = tid + u * 256;         // 0..4095 = 128 rows x 32 float4
        int r = idx >> 5, q = idx & 31;
        cp16(&xt[r * 132 + q * 4], act + (size_t)(n0 + r) * CC + q * 4);
    }
    asm volatile("cp.async.commit_group;" ::: "memory");
    asm volatile("cp.async.wait_group 0;" ::: "memory");
    __syncthreads();

    // --- LN stats: warp w handles rows w*16..w*16+15 (mirrors ln_kernel reduction) ---
    #pragma unroll
    for (int rr = 0; rr < 16; rr++) {
        int r = wid * 16 + rr;
        float4 vv = *(const float4*)(&xt[r * 132 + lane * 4]);
        float s  = vv.x + vv.y + vv.z + vv.w;
        float sq = vv.x*vv.x + vv.y*vv.y + vv.z*vv.z + vv.w*vv.w;
        #pragma unroll
        for (int o = 16; o > 0; o >>= 1) {
            s  += __shfl_xor_sync(0xffffffffu, s,  o);
            sq += __shfl_xor_sync(0xffffffffu, sq, o);
        }
        if (lane == 0) {
            float mean = s * (1.0f / CC);
            mu[r] = mean;
            rs[r] = rsqrtf(sq * (1.0f / CC) - mean * mean + 1e-5f);
        }
    }
    __syncthreads();

    // --- normalize + tf32-round in place ---
    #pragma unroll
    for (int u = 0; u < 16; u++) {
        int idx = tid + u * 256;
        int r = idx >> 5, q = idx & 31;
        float m = mu[r], ir = rs[r];
        float4 vv = *(const float4*)(&xt[r * 132 + q * 4]);
        vv.x = tf32r((vv.x - m) * ir * scb[q * 4 + 0] + scb[128 + q * 4 + 0]);
        vv.y = tf32r((vv.y - m) * ir * scb[q * 4 + 1] + scb[128 + q * 4 + 1]);
        vv.z = tf32r((vv.z - m) * ir * scb[q * 4 + 2] + scb[128 + q * 4 + 2]);
        vv.w = tf32r((vv.w - m) * ir * scb[q * 4 + 3] + scb[128 + q * 4 + 3]);
        *(float4*)(&xt[r * 132 + q * 4]) = vv;
    }
    __syncthreads();

    // --- mainloop: weights double-buffered, X resident in xt ---
    float acc[8][4], accg[8][4];
    #pragma unroll
    for (int t = 0; t < 8; t++)
        #pragma unroll
        for (int q = 0; q < 4; q++) { acc[t][q] = 0.0f; accg[t][q] = 0.0f; }

    {
        int k = tid >> 4, q = tid & 15;
        cp16(&ws0[k * 72 + q * 4],  W  + (size_t)k * CC + q * 4);
        cp16(&wgs0[k * 72 + q * 4], Wg + (size_t)k * CC + q * 4);
        asm volatile("cp.async.commit_group;" ::: "memory");
    }

    for (int ch = 0; ch < 8; ch++) {
        asm volatile("cp.async.wait_group 0;" ::: "memory");
        __syncthreads();
        if (ch < 7) {
            int k0 = (ch + 1) * 16;
            int buf = (ch + 1) & 1;
            int k = tid >> 4, q = tid & 15;
            cp16(&ws0[buf * 1152 + k * 72 + q * 4],  W  + (size_t)(k0 + k) * CC + q * 4);
            cp16(&wgs0[buf * 1152 + k * 72 + q * 4], Wg + (size_t)(k0 + k) * CC + q * 4);
            asm volatile("cp.async.commit_group;" ::: "memory");
        }
        const float* Ws  = ws0  + (ch & 1) * 1152;
        const float* Wgs = wgs0 + (ch & 1) * 1152;
        const int kb = ch * 16;
        #pragma unroll
        for (int ks = 0; ks < 16; ks += 8) {
            uint32_t a[4][4], b[2][2], bg[2][2];
            #pragma unroll
            for (int mt = 0; mt < 4; mt++) {
                int row = warp_m * 64 + mt * 16 + lr;
                int k = kb + ks + lc;
                a[mt][0] = __float_as_uint(xt[row * 132 + k]);
                a[mt][1] = __float_as_uint(xt[(row + 8) * 132 + k]);
                a[mt][2] = __float_as_uint(xt[row * 132 + k + 4]);
                a[mt][3] = __float_as_uint(xt[(row + 8) * 132 + k + 4]);
            }
            #pragma unroll
            for (int nt = 0; nt < 2; nt++) {
                int nb = warp_n * 16 + nt * 8 + lr;
                b[nt][0]  = __float_as_uint(Ws[(ks + lc) * 72 + nb]);
                b[nt][1]  = __float_as_uint(Ws[(ks + 4 + lc) * 72 + nb]);
                bg[nt][0] = __float_as_uint(Wgs[(ks + lc) * 72 + nb]);
                bg[nt][1] = __float_as_uint(Wgs[(ks + 4 + lc) * 72 + nb]);
            }
            #pragma unroll
            for (int mt = 0; mt < 4; mt++)
                #pragma unroll
                for (int nt = 0; nt < 2; nt++) {
                    mma_tf32(acc[mt * 2 + nt], a[mt], b[nt]);
                    mma_tf32(accg[mt * 2 + nt], a[mt], bg[nt]);
                }
        }
    }
    __syncthreads();   // mainloop xt reads done before tile reuse

    if (v < 4) {
        // epilogue: gate+mask into 128x64 tile (reuses xt), transposed c-major write (k-interleaved)
        float (*tile)[68] = (float (*)[68])sm;
        #pragma unroll
        for (int mt = 0; mt < 4; mt++) {
            #pragma unroll
            for (int nt = 0; nt < 2; nt++) {
                int col = warp_n * 16 + nt * 8 + lc * 2;
                float2 bb  = *(const float2*)(B + col);
                float2 bbg = *(const float2*)(Bg + col);
                #pragma unroll
                for (int h = 0; h < 2; h++) {
                    int rl = warp_m * 64 + mt * 16 + lr + h * 8;
                    int n = n0 + rl;
                    float pm = mask[n >> 9] * mask[n & 511];
                    float vx = (acc[mt * 2 + nt][h * 2 + 0] + bb.x) * pm
                             * sigf(accg[mt * 2 + nt][h * 2 + 0] + bbg.x);
                    float vy = (acc[mt * 2 + nt][h * 2 + 1] + bb.y) * pm
                             * sigf(accg[mt * 2 + nt][h * 2 + 1] + bbg.y);
                    tile[rl][col]     = tf32r(vx);
                    tile[rl][col + 1] = tf32r(vy);
                }
            }
        }
        __syncthreads();
        const int O8[8] = {0, 4, 1, 5, 2, 6, 3, 7};
        int c = tid >> 2;
        int h = tid & 3;
        float* dst = dstT + (size_t)c * NROWS + n0 + h * 32;
        #pragma unroll
        for (int q = 0; q < 8; q++) {
            int g8 = (q >> 1) * 8;
            int e  = (q & 1) * 4;
            float4 vv;
            vv.x = tile[h * 32 + g8 + O8[e + 0]][c];
            vv.y = tile[h * 32 + g8 + O8[e + 1]][c];
            vv.z = tile[h * 32 + g8 + O8[e + 2]][c];
            vv.w = tile[h * 32 + g8 + O8[e + 3]][c];
            *(float4*)(dst + q * 4) = vv;
        }
    } else {
        // fgate epilogue: sigmoid, n-major; acc -> cols 0-63, accg -> cols 64-127
        #pragma unroll
        for (int mt = 0; mt < 4; mt++) {
            #pragma unroll
            for (int nt = 0; nt < 2; nt++) {
                int col = warp_n * 16 + nt * 8 + lc * 2;
                float2 bb  = *(const float2*)(B + col);
                float2 bbg = *(const float2*)(Bg + col);
                #pragma unroll
                for (int h = 0; h < 2; h++) {
                    int row = n0 + warp_m * 64 + mt * 16 + lr + h * 8;
                    float2 v0, v1;
                    v0.x = sigf(acc[mt * 2 + nt][h * 2 + 0] + bb.x);
                    v0.y = sigf(acc[mt * 2 + nt][h * 2 + 1] + bb.y);
                    v1.x = sigf(accg[mt * 2 + nt][h * 2 + 0] + bbg.x);
                    v1.y = sigf(accg[mt * 2 + nt][h * 2 + 1] + bbg.y);
                    *(float2*)(g_Fg + (size_t)row * CC + col)      = v0;
                    *(float2*)(g_Fg + (size_t)row * CC + col + 64) = v1;
                }
            }
        }
    }
}

// ---------------- einsum: cp.async double-buffered + k-interleaved LDS.64 fragments ----------------
__global__ void __launch_bounds__(128, 3) einsum_mma()
{
    __shared__ __align__(16) float As[2][128 * 24];
    __shared__ __align__(16) float Bs[2][128 * 24];
    const int c  = blockIdx.z;
    const int i0 = blockIdx.x * 128;
    const int j0 = blockIdx.y * 128;
    const int tid  = threadIdx.x;
    const int wid  = tid >> 5;
    const int lane = tid & 31;
    const int warp_m = wid >> 1;
    const int warp_n = wid & 1;
    const int lr = lane >> 2;
    const int lc = lane & 3;

    const float* Ap = g_Lt + (size_t)c * NROWS + (size_t)i0 * 512;
    const float* Bp = g_Rt + (size_t)c * NROWS + (size_t)j0 * 512;

    const int ldr0 = tid >> 2;
    const int ldq  = tid & 3;

    float acc[32][4];
    #pragma unroll
    for (int t = 0; t < 32; t++)
        #pragma unroll
        for (int q = 0; q < 4; q++) acc[t][q] = 0.0f;

    #pragma unroll
    for (int u = 0; u < 4; u++) {
        int r = ldr0 + u * 32;
        cp16(&As[0][r * 24 + ldq * 4], Ap + (size_t)r * 512 + ldq * 4);
        cp16(&Bs[0][r * 24 + ldq * 4], Bp + (size_t)r * 512 + ldq * 4);
    }
    asm volatile("cp.async.commit_group;" ::: "memory");

    for (int ch = 0; ch < 32; ch++) {
        asm volatile("cp.async.wait_group 0;" ::: "memory");
        __syncthreads();
        if (ch < 31) {
            int k1 = (ch + 1) * 16;
            int nb = (ch + 1) & 1;
            #pragma unroll
            for (int u = 0; u < 4; u++) {
                int r = ldr0 + u * 32;
                cp16(&As[nb][r * 24 + ldq * 4], Ap + (size_t)r * 512 + k1 + ldq * 4);
                cp16(&Bs[nb][r * 24 + ldq * 4], Bp + (size_t)r * 512 + k1 + ldq * 4);
            }
            asm volatile("cp.async.commit_group;" ::: "memory");
        }
        const float* A = As[ch & 1];
        const float* B = Bs[ch & 1];
        #pragma unroll
        for (int ks = 0; ks < 16; ks += 8) {
            uint32_t a[4][4], b[8][2];
            #pragma unroll
            for (int mt = 0; mt < 4; mt++) {
                int rb = (warp_m * 64 + mt * 16 + lr) * 24 + ks + 2 * lc;
                float2 p0 = *(const float2*)(&A[rb]);
                float2 p1 = *(const float2*)(&A[rb + 8 * 24]);
                a[mt][0] = __float_as_uint(p0.x);
                a[mt][1] = __float_as_uint(p1.x);
                a[mt][2] = __float_as_uint(p0.y);
                a[mt][3] = __float_as_uint(p1.y);
            }
            #pragma unroll
            for (int nt = 0; nt < 8; nt++) {
                int rb = (warp_n * 64 + nt * 8 + lr) * 24 + ks + 2 * lc;
                float2 pb = *(const float2*)(&B[rb]);
                b[nt][0] = __float_as_uint(pb.x);
                b[nt][1] = __float_as_uint(pb.y);
            }
            #pragma unroll
            for (int mt = 0; mt < 4; mt++)
                #pragma unroll
                for (int nt = 0; nt < 8; nt++)
                    mma_tf32(acc[mt * 8 + nt], a[mt], b[nt]);
        }
    }

    float* Op = g_Ot + (size_t)c * NROWS;
    #pragma unroll
    for (int mt = 0; mt < 4; mt++) {
        #pragma unroll
        for (int nt = 0; nt < 8; nt++) {
            int col = j0 + warp_n * 64 + nt * 8 + lc * 2;
            #pragma unroll
            for (int h = 0; h < 2; h++) {
                int row = i0 + warp_m * 64 + mt * 16 + lr + h * 8;
                float2 v;
                v.x = acc[mt * 8 + nt][h * 2 + 0];
                v.y = acc[mt * 8 + nt][h * 2 + 1];
                *(float2*)(Op + (size_t)row * 512 + col) = v;
            }
        }
    }
}

// ---------------- fused: load Ot tile (c-major) + LayerNorm + GEMM(w_out) + gate ----------------
__global__ void __launch_bounds__(256) gemm_out_fused(
    const float* __restrict__ B,
    const float* __restrict__ fsc,
    const float* __restrict__ fbi,
    const float* __restrict__ gate,
    float* __restrict__ out)
{
    extern __shared__ float dsm[];
    float* tileA = dsm;                    // 128 c x 129
    float* Xs    = dsm + 128 * 129;        // 128 x 20
    float* Ws    = Xs + 128 * 20;          // 16 x 136
    float* s_mu  = Ws + 16 * 136;          // 128
    float* s_rs  = s_mu + 128;             // 128
    const float* W = g_Wt + 5 * CC * CC;   // pre-rounded

    const int n0   = blockIdx.x * 128;
    const int tid  = threadIdx.x;
    const int wid  = tid >> 5;
    const int lane = tid & 31;
    const int warp_m = wid >> 2;
    const int warp_n = wid & 3;
    const int lr = lane >> 2;
    const int lc = lane & 3;

    #pragma unroll
    for (int u = 0; u < 16; u++) {
        int idx = tid + u * 256;
        int cc = idx >> 5;
        int q  = idx & 31;
        float4 v = *(const float4*)(g_Ot + (size_t)cc * NROWS + n0 + q * 4);
        float* trow = &tileA[cc * 129 + q * 4];
        trow[0] = v.x; trow[1] = v.y; trow[2] = v.z; trow[3] = v.w;
    }
    __syncthreads();

    #pragma unroll
    for (int rr = 0; rr < 16; rr++) {
        int r = wid * 16 + rr;
        float s = 0.0f, sq = 0.0f;
        #pragma unroll
        for (int m = 0; m < 4; m++) {
            float v = tileA[(lane + m * 32) * 129 + r];
            s += v; sq += v * v;
        }
        #pragma unroll
        for (int o = 16; o > 0; o >>= 1) {
            s  += __shfl_xor_sync(0xffffffffu, s,  o);
            sq += __shfl_xor_sync(0xffffffffu, sq, o);
        }
        if (lane == 0) {
            float mean = s * (1.0f / CC);
            s_mu[r] = mean;
            s_rs[r] = rsqrtf(sq * (1.0f / CC) - mean * mean + 1e-5f);
        }
    }
    __syncthreads();

    float acc[16][4];
    #pragma unroll
    for (int t = 0; t < 16; t++)
        #pragma unroll
        for (int q = 0; q < 4; q++) acc[t][q] = 0.0f;

    for (int k0 = 0; k0 < CC; k0 += 16) {
        #pragma unroll
        for (int u = 0; u < 8; u++) {
            int idx = tid + u * 256;
            int kk = idx & 15;
            int r  = idx >> 4;
            float v = (tileA[(k0 + kk) * 129 + r] - s_mu[r]) * s_rs[r]
                      * fsc[k0 + kk] + fbi[k0 + kk];
            Xs[r * 20 + kk] = tf32r(v);
        }
        #pragma unroll
        for (int u = 0; u < 2; u++) {
            int idx = tid + u * 256;
            int k = idx >> 5;
            int q = idx & 31;
            *(float4*)(&Ws[k * 136 + q * 4]) = *(const float4*)(W + (size_t)(k0 + k) * CC + q * 4);
        }
        __syncthreads();
        #pragma unroll
        for (int ks = 0; ks < 16; ks += 8) {
            uint32_t a[4][4], b[4][2];
            #pragma unroll
            for (int mt = 0; mt < 4; mt++) {
                int rb = (warp_m * 64 + mt * 16 + lr) * 20 + ks + lc;
                a[mt][0] = __float_as_uint(Xs[rb]);
                a[mt][1] = __float_as_uint(Xs[rb + 8 * 20]);
                a[mt][2] = __float_as_uint(Xs[rb + 4]);
                a[mt][3] = __float_as_uint(Xs[rb + 8 * 20 + 4]);
            }
            #pragma unroll
            for (int nt = 0; nt < 4; nt++) {
                int nb = warp_n * 32 + nt * 8 + lr;
                b[nt][0] = __float_as_uint(Ws[(ks + lc) * 136 + nb]);
                b[nt][1] = __float_as_uint(Ws[(ks + 4 + lc) * 136 + nb]);
            }
            #pragma unroll
            for (int mt = 0; mt < 4; mt++)
                #pragma unroll
                for (int nt = 0; nt < 4; nt++)
                    mma_tf32(acc[mt * 4 + nt], a[mt], b[nt]);
        }
        __syncthreads();
    }

    #pragma unroll
    for (int mt = 0; mt < 4; mt++) {
        #pragma unroll
        for (int nt = 0; nt < 4; nt++) {
            int col = warp_n * 32 + nt * 8 + lc * 2;
            float2 bb = *(const float2*)(B + col);
            #pragma unroll
            for (int h = 0; h < 2; h++) {
                int row = n0 + warp_m * 64 + mt * 16 + lr + h * 8;
                float2 gv = *(const float2*)(gate + (size_t)row * CC + col);
                float2 v;
                v.x = (acc[mt * 4 + nt][h * 2 + 0] + bb.x) * gv.x;
                v.y = (acc[mt * 4 + nt][h * 2 + 1] + bb.y) * gv.y;
                *(float2*)(out + (size_t)row * CC + col) = v;
            }
        }
    }
}

// ---------------- host launch ----------------
extern "C" void kernel_launch(void* const* d_in, const int* in_sizes, int n_in,
                              void* d_out, int out_size)
{
    const float* act         = (const float*)d_in[0];
    const float* mask        = (const float*)d_in[1];
    const float* norm_scale  = (const float*)d_in[2];
    const float* norm_bias   = (const float*)d_in[3];
    const float* w_left      = (const float*)d_in[4];
    const float* b_left      = (const float*)d_in[5];
    const float* w_right     = (const float*)d_in[6];
    const float* b_right     = (const float*)d_in[7];
    const float* w_lgate     = (const float*)d_in[8];
    const float* b_lgate     = (const float*)d_in[9];
    const float* w_rgate     = (const float*)d_in[10];
    const float* b_rgate     = (const float*)d_in[11];
    const float* fnorm_scale = (const float*)d_in[12];
    const float* fnorm_bias  = (const float*)d_in[13];
    const float* w_out       = (const float*)d_in[14];
    const float* b_out       = (const float*)d_in[15];
    const float* w_fgate     = (const float*)d_in[16];
    const float* b_fgate     = (const float*)d_in[17];

    float* Fg;
    cudaGetSymbolAddress((void**)&Fg, g_Fg);

    const int lp_smem  = (128 * 132 + 2 * 1152 + 2 * 1152 + 128 + 128 + 256) * sizeof(float);
    const int out_smem = (128 * 129 + 128 * 20 + 16 * 136 + 256) * sizeof(float);
    static int attr_set = 0;
    if (!attr_set) {
        cudaFuncSetAttribute(ln_proj,
                             cudaFuncAttributeMaxDynamicSharedMemorySize, lp_smem);
        cudaFuncSetAttribute(gemm_out_fused,
                             cudaFuncAttributeMaxDynamicSharedMemorySize, out_smem);
        attr_set = 1;
    }

    // 0) tf32-round all weights once
    prep_weights<<<(6 * CC * CC) / 256, 256>>>(
        w_left, w_lgate, w_right, w_rgate, w_fgate, w_out);

    // 1) fused LN + projections + gates + mask + fgate -> Lt, Rt, Fg
    ln_proj<<<dim3(5, NROWS / 128), 256, lp_smem>>>(
        act, norm_scale, norm_bias,
        b_left, b_lgate, b_right, b_rgate, b_fgate, mask);

    // 2) einsum on tensor cores -> Ot (c-major)
    einsum_mma<<<dim3(4, 4, CC), 128>>>();

    // 3) fused: LN(Ot) transpose + output projection + final gate
    gemm_out_fused<<<NROWS / 128, 256, out_smem>>>(
        b_out, fnorm_scale, fnorm_bias, Fg, (float*)d_out);
}

// round 13
// speedup vs baseline: 1.1416x; 1.1416x over previous
#include <cuda_runtime.h>
#include <cstdint>
#include <math.h>

#define LL 512
#define CC 128
#define NROWS (LL*LL)   // 262144

// ---- scratch ----
__device__ float g_X[NROWS*CC];     // normalized input, tf32-rounded (n-major)
__device__ float g_Wt[6*CC*CC];     // tf32-rounded weights: w_l, w_lg, w_r, w_rg, w_fgate, w_out
__device__ float g_Lt[CC*NROWS];    // left  gated+masked, c-major planes, k-interleaved [0,4,1,5,2,6,3,7]/8-group
__device__ float g_Rt[CC*NROWS];    // right gated+masked, same layout
__device__ float g_Fg[NROWS*CC];    // sigmoid(final gate), n-major
__device__ float g_Ot[CC*NROWS];    // einsum output, c-major planes [c][i*512+j]

__device__ __forceinline__ float sigf(float x) {
    return 1.0f / (1.0f + __expf(-x));
}
__device__ __forceinline__ float tf32r(float x) {
    uint32_t y;
    asm("cvt.rna.tf32.f32 %0, %1;" : "=r"(y) : "f"(x));
    return __uint_as_float(y);
}
__device__ __forceinline__ void mma_tf32(float* c, const uint32_t* a, const uint32_t* b) {
    asm volatile(
        "mma.sync.aligned.m16n8k8.row.col.f32.tf32.tf32.f32 "
        "{%0,%1,%2,%3}, {%4,%5,%6,%7}, {%8,%9}, {%0,%1,%2,%3};"
        : "+f"(c[0]), "+f"(c[1]), "+f"(c[2]), "+f"(c[3])
        : "r"(a[0]), "r"(a[1]), "r"(a[2]), "r"(a[3]), "r"(b[0]), "r"(b[1]));
}
__device__ __forceinline__ void cp16(float* smem, const float* gmem) {
    uint32_t s = (uint32_t)__cvta_generic_to_shared(smem);
    asm volatile("cp.async.ca.shared.global [%0], [%1], 16;" :: "r"(s), "l"(gmem));
}

// ---------------- weight prep: tf32-round all 6 weights once ----------------
__global__ void prep_weights(const float* __restrict__ w0, const float* __restrict__ w1,
                             const float* __restrict__ w2, const float* __restrict__ w3,
                             const float* __restrict__ w4, const float* __restrict__ w5)
{
    int i = blockIdx.x * 256 + threadIdx.x;       // 0 .. 98303
    int w = i >> 14;
    int e = i & 16383;
    const float* src = (w == 0) ? w0 : (w == 1) ? w1 : (w == 2) ? w2
                     : (w == 3) ? w3 : (w == 4) ? w4 : w5;
    g_Wt[i] = tf32r(src[e]);
}

// ---------------- LayerNorm: one warp per row of 128; writes tf32-rounded ----------------
__global__ void ln_kernel(const float* __restrict__ in,
                          const float* __restrict__ scale,
                          const float* __restrict__ bias,
                          float* __restrict__ out)
{
    int warp = (blockIdx.x * blockDim.x + threadIdx.x) >> 5;
    int lane = threadIdx.x & 31;
    if (warp >= NROWS) return;
    const float4 v = *(const float4*)(in + (size_t)warp * CC + lane * 4);
    float s  = v.x + v.y + v.z + v.w;
    float sq = v.x*v.x + v.y*v.y + v.z*v.z + v.w*v.w;
    #pragma unroll
    for (int o = 16; o > 0; o >>= 1) {
        s  += __shfl_xor_sync(0xffffffffu, s,  o);
        sq += __shfl_xor_sync(0xffffffffu, sq, o);
    }
    float mean = s * (1.0f / CC);
    float var  = sq * (1.0f / CC) - mean * mean;
    float rstd = rsqrtf(var + 1e-5f);
    float4 sc = *(const float4*)(scale + lane * 4);
    float4 bi = *(const float4*)(bias  + lane * 4);
    float4 r;
    r.x = tf32r((v.x - mean) * rstd * sc.x + bi.x);
    r.y = tf32r((v.y - mean) * rstd * sc.y + bi.y);
    r.z = tf32r((v.z - mean) * rstd * sc.z + bi.z);
    r.w = tf32r((v.w - mean) * rstd * sc.w + bi.w);
    *(float4*)(out + (size_t)warp * CC + lane * 4) = r;
}

// ---------------- Fg GEMM (cp.async pipelined): out = sigmoid(X@W + b) ----------------
__global__ void __launch_bounds__(256) gemm_mma_s(
    const float* __restrict__ X,
    const float* __restrict__ B,
    float* __restrict__ out)
{
    __shared__ __align__(16) float sbuf[2*2560 + 2*2176];
    float* Xs0 = sbuf;             // [2][128*20]
    float* Ws0 = sbuf + 5120;      // [2][16*136]
    const float* W = g_Wt + 4 * CC * CC;
    const int r0   = blockIdx.x * 128;
    const int tid  = threadIdx.x;
    const int wid  = tid >> 5;
    const int lane = tid & 31;
    const int warp_m = wid >> 2;
    const int warp_n = wid & 3;
    const int lr = lane >> 2;
    const int lc = lane & 3;

    float acc[16][4];
    #pragma unroll
    for (int t = 0; t < 16; t++)
        #pragma unroll
        for (int q = 0; q < 4; q++) acc[t][q] = 0.0f;

    {
        #pragma unroll
        for (int u = 0; u < 2; u++) {
            int idx = tid + u * 256;
            int r = idx >> 2, q = idx & 3;
            cp16(&Xs0[r * 20 + q * 4], X + (size_t)(r0 + r) * CC + q * 4);
        }
        #pragma unroll
        for (int u = 0; u < 2; u++) {
            int idx = tid + u * 256;
            int k = idx >> 5, q = idx & 31;
            cp16(&Ws0[k * 136 + q * 4], W + (size_t)k * CC + q * 4);
        }
        asm volatile("cp.async.commit_group;" ::: "memory");
    }

    for (int ch = 0; ch < 8; ch++) {
        asm volatile("cp.async.wait_group 0;" ::: "memory");
        __syncthreads();
        if (ch < 7) {
            int k0 = (ch + 1) * 16;
            int buf = (ch + 1) & 1;
            #pragma unroll
            for (int u = 0; u < 2; u++) {
                int idx = tid + u * 256;
                int r = idx >> 2, q = idx & 3;
                cp16(&Xs0[buf * 2560 + r * 20 + q * 4], X + (size_t)(r0 + r) * CC + k0 + q * 4);
            }
            #pragma unroll
            for (int u = 0; u < 2; u++) {
                int idx = tid + u * 256;
                int k = idx >> 5, q = idx & 31;
                cp16(&Ws0[buf * 2176 + k * 136 + q * 4], W + (size_t)(k0 + k) * CC + q * 4);
            }
            asm volatile("cp.async.commit_group;" ::: "memory");
        }
        const float* Xs = Xs0 + (ch & 1) * 2560;
        const float* Ws = Ws0 + (ch & 1) * 2176;
        #pragma unroll
        for (int ks = 0; ks < 16; ks += 8) {
            uint32_t a[4][4], b[4][2];
            #pragma unroll
            for (int mt = 0; mt < 4; mt++) {
                int rb = (warp_m * 64 + mt * 16 + lr) * 20 + ks + lc;
                a[mt][0] = __float_as_uint(Xs[rb]);
                a[mt][1] = __float_as_uint(Xs[rb + 8 * 20]);
                a[mt][2] = __float_as_uint(Xs[rb + 4]);
                a[mt][3] = __float_as_uint(Xs[rb + 8 * 20 + 4]);
            }
            #pragma unroll
            for (int nt = 0; nt < 4; nt++) {
                int nb = warp_n * 32 + nt * 8 + lr;
                b[nt][0] = __float_as_uint(Ws[(ks + lc) * 136 + nb]);
                b[nt][1] = __float_as_uint(Ws[(ks + 4 + lc) * 136 + nb]);
            }
            #pragma unroll
            for (int mt = 0; mt < 4; mt++)
                #pragma unroll
                for (int nt = 0; nt < 4; nt++)
                    mma_tf32(acc[mt * 4 + nt], a[mt], b[nt]);
        }
    }

    #pragma unroll
    for (int mt = 0; mt < 4; mt++) {
        #pragma unroll
        for (int nt = 0; nt < 4; nt++) {
            int col = warp_n * 32 + nt * 8 + lc * 2;
            float2 bb = *(const float2*)(B + col);
            #pragma unroll
            for (int h = 0; h < 2; h++) {
                int row = r0 + warp_m * 64 + mt * 16 + lr + h * 8;
                float2 v;
                v.x = sigf(acc[mt * 4 + nt][h * 2 + 0] + bb.x);
                v.y = sigf(acc[mt * 4 + nt][h * 2 + 1] + bb.y);
                *(float2*)(out + (size_t)row * CC + col) = v;
            }
        }
    }
}

// ---------------- fused projection + gate + mask + c-major transpose (pipelined) ----------------
// grid = (4, 2048): blockIdx.x = (sel<<1)|half (fast dim -> X tile L2 reuse).
__global__ void __launch_bounds__(256) proj_lr(
    const float* __restrict__ b_l,  const float* __restrict__ b_lg,
    const float* __restrict__ b_r,  const float* __restrict__ b_rg,
    const float* __restrict__ mask)
{
    __shared__ __align__(16) float sbuf[2*2560 + 4*1152];   // 9728 floats; epilogue tile (8704) reuses
    float* Xs0  = sbuf;            // [2][128*20]
    float* Ws0  = sbuf + 5120;     // [2][16*72]
    float* Wgs0 = sbuf + 7424;     // [2][16*72]

    const int sel  = blockIdx.x >> 1;
    const int half = blockIdx.x & 1;
    const float* W  = g_Wt + (sel ? 2 : 0) * CC * CC + half * 64;
    const float* Wg = g_Wt + (sel ? 3 : 1) * CC * CC + half * 64;
    const float* B  = (sel ? b_r  : b_l)  + half * 64;
    const float* Bg = (sel ? b_rg : b_lg) + half * 64;
    float* dstT = (sel ? g_Rt : g_Lt) + (size_t)(half * 64) * NROWS;

    const int n0   = blockIdx.y * 128;
    const int tid  = threadIdx.x;
    const int wid  = tid >> 5;
    const int lane = tid & 31;
    const int warp_m = wid >> 2;
    const int warp_n = wid & 3;
    const int lr = lane >> 2;
    const int lc = lane & 3;

    float acc[8][4], accg[8][4];
    #pragma unroll
    for (int t = 0; t < 8; t++)
        #pragma unroll
        for (int q = 0; q < 4; q++) { acc[t][q] = 0.0f; accg[t][q] = 0.0f; }

    {
        #pragma unroll
        for (int u = 0; u < 2; u++) {
            int idx = tid + u * 256;
            int r = idx >> 2, q = idx & 3;
            cp16(&Xs0[r * 20 + q * 4], g_X + (size_t)(n0 + r) * CC + q * 4);
        }
        int k = tid >> 4, q = tid & 15;
        cp16(&Ws0[k * 72 + q * 4],  W  + (size_t)k * CC + q * 4);
        cp16(&Wgs0[k * 72 + q * 4], Wg + (size_t)k * CC + q * 4);
        asm volatile("cp.async.commit_group;" ::: "memory");
    }

    for (int ch = 0; ch < 8; ch++) {
        asm volatile("cp.async.wait_group 0;" ::: "memory");
        __syncthreads();
        if (ch < 7) {
            int k0 = (ch + 1) * 16;
            int buf = (ch + 1) & 1;
            #pragma unroll
            for (int u = 0; u < 2; u++) {
                int idx = tid + u * 256;
                int r = idx >> 2, q = idx & 3;
                cp16(&Xs0[buf * 2560 + r * 20 + q * 4], g_X + (size_t)(n0 + r) * CC + k0 + q * 4);
            }
            int k = tid >> 4, q = tid & 15;
            cp16(&Ws0[buf * 1152 + k * 72 + q * 4],  W  + (size_t)(k0 + k) * CC + q * 4);
            cp16(&Wgs0[buf * 1152 + k * 72 + q * 4], Wg + (size_t)(k0 + k) * CC + q * 4);
            asm volatile("cp.async.commit_group;" ::: "memory");
        }
        const float* Xs  = Xs0  + (ch & 1) * 2560;
        const float* Ws  = Ws0  + (ch & 1) * 1152;
        const float* Wgs = Wgs0 + (ch & 1) * 1152;
        #pragma unroll
        for (int ks = 0; ks < 16; ks += 8) {
            uint32_t a[4][4], b[2][2], bg[2][2];
            #pragma unroll
            for (int mt = 0; mt < 4; mt++) {
                int rb = (warp_m * 64 + mt * 16 + lr) * 20 + ks + lc;
                a[mt][0] = __float_as_uint(Xs[rb]);
                a[mt][1] = __float_as_uint(Xs[rb + 8 * 20]);
                a[mt][2] = __float_as_uint(Xs[rb + 4]);
                a[mt][3] = __float_as_uint(Xs[rb + 8 * 20 + 4]);
            }
            #pragma unroll
            for (int nt = 0; nt < 2; nt++) {
                int nb = warp_n * 16 + nt * 8 + lr;
                b[nt][0]  = __float_as_uint(Ws[(ks + lc) * 72 + nb]);
                b[nt][1]  = __float_as_uint(Ws[(ks + 4 + lc) * 72 + nb]);
                bg[nt][0] = __float_as_uint(Wgs[(ks + lc) * 72 + nb]);
                bg[nt][1] = __float_as_uint(Wgs[(ks + 4 + lc) * 72 + nb]);
            }
            #pragma unroll
            for (int mt = 0; mt < 4; mt++)
                #pragma unroll
                for (int nt = 0; nt < 2; nt++) {
                    mma_tf32(acc[mt * 2 + nt], a[mt], b[nt]);
                    mma_tf32(accg[mt * 2 + nt], a[mt], bg[nt]);
                }
        }
    }
    __syncthreads();

    // epilogue: gate+mask into 128x64 smem tile, then transposed c-major write (k-interleaved)
    float (*tile)[68] = (float (*)[68])sbuf;
    #pragma unroll
    for (int mt = 0; mt < 4; mt++) {
        #pragma unroll
        for (int nt = 0; nt < 2; nt++) {
            int col = warp_n * 16 + nt * 8 + lc * 2;
            float2 bb  = *(const float2*)(B + col);
            float2 bbg = *(const float2*)(Bg + col);
            #pragma unroll
            for (int h = 0; h < 2; h++) {
                int rl = warp_m * 64 + mt * 16 + lr + h * 8;
                int n = n0 + rl;
                float pm = mask[n >> 9] * mask[n & 511];
                float vx = (acc[mt * 2 + nt][h * 2 + 0] + bb.x) * pm
                         * sigf(accg[mt * 2 + nt][h * 2 + 0] + bbg.x);
                float vy = (acc[mt * 2 + nt][h * 2 + 1] + bb.y) * pm
                         * sigf(accg[mt * 2 + nt][h * 2 + 1] + bbg.y);
                tile[rl][col]     = tf32r(vx);
                tile[rl][col + 1] = tf32r(vy);
            }
        }
    }
    __syncthreads();
    {
        const int O8[8] = {0, 4, 1, 5, 2, 6, 3, 7};
        int c = tid >> 2;
        int h = tid & 3;
        float* dst = dstT + (size_t)c * NROWS + n0 + h * 32;
        #pragma unroll
        for (int q = 0; q < 8; q++) {
            int g8 = (q >> 1) * 8;
            int e  = (q & 1) * 4;
            float4 v;
            v.x = tile[h * 32 + g8 + O8[e + 0]][c];
            v.y = tile[h * 32 + g8 + O8[e + 1]][c];
            v.z = tile[h * 32 + g8 + O8[e + 2]][c];
            v.w = tile[h * 32 + g8 + O8[e + 3]][c];
            *(float4*)(dst + q * 4) = v;
        }
    }
}

// ---------------- einsum: cp.async double-buffered + k-interleaved LDS.64 fragments ----------------
__global__ void __launch_bounds__(128, 3) einsum_mma()
{
    __shared__ __align__(16) float As[2][128 * 24];
    __shared__ __align__(16) float Bs[2][128 * 24];
    const int c  = blockIdx.z;
    const int i0 = blockIdx.x * 128;
    const int j0 = blockIdx.y * 128;
    const int tid  = threadIdx.x;
    const int wid  = tid >> 5;
    const int lane = tid & 31;
    const int warp_m = wid >> 1;
    const int warp_n = wid & 1;
    const int lr = lane >> 2;
    const int lc = lane & 3;

    const float* Ap = g_Lt + (size_t)c * NROWS + (size_t)i0 * 512;
    const float* Bp = g_Rt + (size_t)c * NROWS + (size_t)j0 * 512;

    const int ldr0 = tid >> 2;
    const int ldq  = tid & 3;

    float acc[32][4];
    #pragma unroll
    for (int t = 0; t < 32; t++)
        #pragma unroll
        for (int q = 0; q < 4; q++) acc[t][q] = 0.0f;

    #pragma unroll
    for (int u = 0; u < 4; u++) {
        int r = ldr0 + u * 32;
        cp16(&As[0][r * 24 + ldq * 4], Ap + (size_t)r * 512 + ldq * 4);
        cp16(&Bs[0][r * 24 + ldq * 4], Bp + (size_t)r * 512 + ldq * 4);
    }
    asm volatile("cp.async.commit_group;" ::: "memory");

    for (int ch = 0; ch < 32; ch++) {
        asm volatile("cp.async.wait_group 0;" ::: "memory");
        __syncthreads();
        if (ch < 31) {
            int k1 = (ch + 1) * 16;
            int nb = (ch + 1) & 1;
            #pragma unroll
            for (int u = 0; u < 4; u++) {
                int r = ldr0 + u * 32;
                cp16(&As[nb][r * 24 + ldq * 4], Ap + (size_t)r * 512 + k1 + ldq * 4);
                cp16(&Bs[nb][r * 24 + ldq * 4], Bp + (size_t)r * 512 + k1 + ldq * 4);
            }
            asm volatile("cp.async.commit_group;" ::: "memory");
        }
        const float* A = As[ch & 1];
        const float* B = Bs[ch & 1];
        #pragma unroll
        for (int ks = 0; ks < 16; ks += 8) {
            uint32_t a[4][4], b[8][2];
            #pragma unroll
            for (int mt = 0; mt < 4; mt++) {
                int rb = (warp_m * 64 + mt * 16 + lr) * 24 + ks + 2 * lc;
                float2 p0 = *(const float2*)(&A[rb]);
                float2 p1 = *(const float2*)(&A[rb + 8 * 24]);
                a[mt][0] = __float_as_uint(p0.x);
                a[mt][1] = __float_as_uint(p1.x);
                a[mt][2] = __float_as_uint(p0.y);
                a[mt][3] = __float_as_uint(p1.y);
            }
            #pragma unroll
            for (int nt = 0; nt < 8; nt++) {
                int rb = (warp_n * 64 + nt * 8 + lr) * 24 + ks + 2 * lc;
                float2 pb = *(const float2*)(&B[rb]);
                b[nt][0] = __float_as_uint(pb.x);
                b[nt][1] = __float_as_uint(pb.y);
            }
            #pragma unroll
            for (int mt = 0; mt < 4; mt++)
                #pragma unroll
                for (int nt = 0; nt < 8; nt++)
                    mma_tf32(acc[mt * 8 + nt], a[mt], b[nt]);
        }
    }

    float* Op = g_Ot + (size_t)c * NROWS;
    #pragma unroll
    for (int mt = 0; mt < 4; mt++) {
        #pragma unroll
        for (int nt = 0; nt < 8; nt++) {
            int col = j0 + warp_n * 64 + nt * 8 + lc * 2;
            #pragma unroll
            for (int h = 0; h < 2; h++) {
                int row = i0 + warp_m * 64 + mt * 16 + lr + h * 8;
                float2 v;
                v.x = acc[mt * 8 + nt][h * 2 + 0];
                v.y = acc[mt * 8 + nt][h * 2 + 1];
                *(float2*)(Op + (size_t)row * 512 + col) = v;
            }
        }
    }
}

// ---------------- fused: Ot tile + in-place LN + GEMM(w_out) + gate ----------------
// tileA stride 132: float4-aligned rows, conflict-free direct A-fragment reads
// (bank of tileA[k*132+n] = (4k+n) mod 32 -> 4*lc+lr distinct over the warp).
__global__ void __launch_bounds__(256) gemm_out_fused(
    const float* __restrict__ B,
    const float* __restrict__ fsc,
    const float* __restrict__ fbi,
    const float* __restrict__ gate,
    float* __restrict__ out)
{
    extern __shared__ float dsm[];
    float* tileA = dsm;                    // 128 c x 132 (16896)
    float* Ws0   = dsm + 16896;            // [2][16*136] (4352)
    float* s_mu  = Ws0 + 4352;             // 128
    float* s_rs  = s_mu + 128;             // 128
    float* s_sc  = s_rs + 128;             // 128 fsc
    float* s_bi  = s_sc + 128;             // 128 fbi
    const float* W = g_Wt + 5 * CC * CC;   // pre-rounded

    const int n0   = blockIdx.x * 128;
    const int tid  = threadIdx.x;
    const int wid  = tid >> 5;
    const int lane = tid & 31;
    const int warp_m = wid >> 2;
    const int warp_n = wid & 3;
    const int lr = lane >> 2;
    const int lc = lane & 3;

    // load Ot tile (c-major rows, float4-aligned) + LN params
    if (tid < 128) { s_sc[tid] = fsc[tid]; }
    else           { s_bi[tid - 128] = fbi[tid - 128]; }
    #pragma unroll
    for (int u = 0; u < 16; u++) {
        int idx = tid + u * 256;      // 0..4095 = 128c x 32 float4
        int cc = idx >> 5;
        int q  = idx & 31;
        cp16(&tileA[cc * 132 + q * 4], g_Ot + (size_t)cc * NROWS + n0 + q * 4);
    }
    asm volatile("cp.async.commit_group;" ::: "memory");
    asm volatile("cp.async.wait_group 0;" ::: "memory");
    __syncthreads();

    // LN stats over columns (row n of the logical [n][c] matrix)
    #pragma unroll
    for (int rr = 0; rr < 16; rr++) {
        int r = wid * 16 + rr;
        float s = 0.0f, sq = 0.0f;
        #pragma unroll
        for (int m = 0; m < 4; m++) {
            float v = tileA[(lane + m * 32) * 132 + r];
            s += v; sq += v * v;
        }
        #pragma unroll
        for (int o = 16; o > 0; o >>= 1) {
            s  += __shfl_xor_sync(0xffffffffu, s,  o);
            sq += __shfl_xor_sync(0xffffffffu, sq, o);
        }
        if (lane == 0) {
            float mean = s * (1.0f / CC);
            s_mu[r] = mean;
            s_rs[r] = rsqrtf(sq * (1.0f / CC) - mean * mean + 1e-5f);
        }
    }
    __syncthreads();

    // normalize + tf32-round in place (vectorized along n)
    #pragma unroll
    for (int u = 0; u < 16; u++) {
        int idx = tid + u * 256;
        int cc = idx >> 5;
        int q  = idx & 31;
        float sc = s_sc[cc], bi = s_bi[cc];
        float4 vv = *(const float4*)(&tileA[cc * 132 + q * 4]);
        float4 m4 = *(const float4*)(&s_mu[q * 4]);
        float4 r4 = *(const float4*)(&s_rs[q * 4]);
        vv.x = tf32r((vv.x - m4.x) * r4.x * sc + bi);
        vv.y = tf32r((vv.y - m4.y) * r4.y * sc + bi);
        vv.z = tf32r((vv.z - m4.z) * r4.z * sc + bi);
        vv.w = tf32r((vv.w - m4.w) * r4.w * sc + bi);
        *(float4*)(&tileA[cc * 132 + q * 4]) = vv;
    }

    // prefetch weight chunk 0
    {
        #pragma unroll
        for (int u = 0; u < 2; u++) {
            int idx = tid + u * 256;
            int k = idx >> 5, q = idx & 31;
            cp16(&Ws0[k * 136 + q * 4], W + (size_t)k * CC + q * 4);
        }
        asm volatile("cp.async.commit_group;" ::: "memory");
    }

    float acc[16][4];
    #pragma unroll
    for (int t = 0; t < 16; t++)
        #pragma unroll
        for (int q = 0; q < 4; q++) acc[t][q] = 0.0f;

    for (int ch = 0; ch < 8; ch++) {
        asm volatile("cp.async.wait_group 0;" ::: "memory");
        __syncthreads();
        if (ch < 7) {
            int k0 = (ch + 1) * 16;
            int buf = (ch + 1) & 1;
            #pragma unroll
            for (int u = 0; u < 2; u++) {
                int idx = tid + u * 256;
                int k = idx >> 5, q = idx & 31;
                cp16(&Ws0[buf * 2176 + k * 136 + q * 4], W + (size_t)(k0 + k) * CC + q * 4);
            }
            asm volatile("cp.async.commit_group;" ::: "memory");
        }
        const float* Ws = Ws0 + (ch & 1) * 2176;
        const int kb = ch * 16;
        #pragma unroll
        for (int ks = 0; ks < 16; ks += 8) {
            uint32_t a[4][4], b[4][2];
            #pragma unroll
            for (int mt = 0; mt < 4; mt++) {
                int n = warp_m * 64 + mt * 16 + lr;
                int k = kb + ks + lc;
                a[mt][0] = __float_as_uint(tileA[k * 132 + n]);
                a[mt][1] = __float_as_uint(tileA[k * 132 + n + 8]);
                a[mt][2] = __float_as_uint(tileA[(k + 4) * 132 + n]);
                a[mt][3] = __float_as_uint(tileA[(k + 4) * 132 + n + 8]);
            }
            #pragma unroll
            for (int nt = 0; nt < 4; nt++) {
                int nb = warp_n * 32 + nt * 8 + lr;
                b[nt][0] = __float_as_uint(Ws[(ks + lc) * 136 + nb]);
                b[nt][1] = __float_as_uint(Ws[(ks + 4 + lc) * 136 + nb]);
            }
            #pragma unroll
            for (int mt = 0; mt < 4; mt++)
                #pragma unroll
                for (int nt = 0; nt < 4; nt++)
                    mma_tf32(acc[mt * 4 + nt], a[mt], b[nt]);
        }
    }

    #pragma unroll
    for (int mt = 0; mt < 4; mt++) {
        #pragma unroll
        for (int nt = 0; nt < 4; nt++) {
            int col = warp_n * 32 + nt * 8 + lc * 2;
            float2 bb = *(const float2*)(B + col);
            #pragma unroll
            for (int h = 0; h < 2; h++) {
                int row = n0 + warp_m * 64 + mt * 16 + lr + h * 8;
                float2 gv = *(const float2*)(gate + (size_t)row * CC + col);
                float2 v;
                v.x = (acc[mt * 4 + nt][h * 2 + 0] + bb.x) * gv.x;
                v.y = (acc[mt * 4 + nt][h * 2 + 1] + bb.y) * gv.y;
                *(float2*)(out + (size_t)row * CC + col) = v;
            }
        }
    }
}

// ---------------- host launch ----------------
extern "C" void kernel_launch(void* const* d_in, const int* in_sizes, int n_in,
                              void* d_out, int out_size)
{
    const float* act         = (const float*)d_in[0];
    const float* mask        = (const float*)d_in[1];
    const float* norm_scale  = (const float*)d_in[2];
    const float* norm_bias   = (const float*)d_in[3];
    const float* w_left      = (const float*)d_in[4];
    const float* b_left      = (const float*)d_in[5];
    const float* w_right     = (const float*)d_in[6];
    const float* b_right     = (const float*)d_in[7];
    const float* w_lgate     = (const float*)d_in[8];
    const float* b_lgate     = (const float*)d_in[9];
    const float* w_rgate     = (const float*)d_in[10];
    const float* b_rgate     = (const float*)d_in[11];
    const float* fnorm_scale = (const float*)d_in[12];
    const float* fnorm_bias  = (const float*)d_in[13];
    const float* w_out       = (const float*)d_in[14];
    const float* b_out       = (const float*)d_in[15];
    const float* w_fgate     = (const float*)d_in[16];
    const float* b_fgate     = (const float*)d_in[17];

    float *X, *Fg;
    cudaGetSymbolAddress((void**)&X,  g_X);
    cudaGetSymbolAddress((void**)&Fg, g_Fg);

    const int out_smem = (128 * 132 + 2 * 2176 + 4 * 128) * sizeof(float);
    static int attr_set = 0;
    if (!attr_set) {
        cudaFuncSetAttribute(gemm_out_fused,
                             cudaFuncAttributeMaxDynamicSharedMemorySize, out_smem);
        attr_set = 1;
    }

    // 0) tf32-round all weights once
    prep_weights<<<(6 * CC * CC) / 256, 256>>>(
        w_left, w_lgate, w_right, w_rgate, w_fgate, w_out);

    // 1) x = LN(act), tf32-rounded
    ln_kernel<<<NROWS / 8, 256>>>(act, norm_scale, norm_bias, X);

    // 2) fused projections + gates + mask -> Lt, Rt (pipelined)
    proj_lr<<<dim3(4, NROWS / 128), 256>>>(
        b_left, b_lgate, b_right, b_rgate, mask);

    // 3) final-gate projection: Fg = sigmoid(X @ w_fgate + b_fgate) (pipelined)
    gemm_mma_s<<<NROWS / 128, 256>>>(X, b_fgate, Fg);

    // 4) einsum on tensor cores -> Ot (c-major)
    einsum_mma<<<dim3(4, 4, CC), 128>>>();

    // 5+6) fused: in-place LN(Ot) + output projection + final gate
    gemm_out_fused<<<NROWS / 128, 256, out_smem>>>(
        b_out, fnorm_scale, fnorm_bias, Fg, (float*)d_out);
}

// round 14
// speedup vs baseline: 1.2047x; 1.0552x over previous
#include <cuda_runtime.h>
#include <cstdint>
#include <math.h>

#define LL 512
#define CC 128
#define NROWS (LL*LL)   // 262144

// ---- scratch ----
__device__ float g_X[NROWS*CC];     // normalized input, tf32-rounded (n-major)
__device__ float g_Wt[6*CC*CC];     // tf32-rounded weights: w_l, w_lg, w_r, w_rg, w_fgate, w_out
__device__ float g_Lt[CC*NROWS];    // left  gated+masked, c-major planes, k-interleaved [0,4,1,5,2,6,3,7]/8-group
__device__ float g_Rt[CC*NROWS];    // right gated+masked, same layout
__device__ float g_Fg[NROWS*CC];    // sigmoid(final gate), n-major
__device__ float g_Ot[CC*NROWS];    // einsum output, c-major planes [c][i*512+j]

__device__ __forceinline__ float sigf(float x) {
    return 1.0f / (1.0f + __expf(-x));
}
__device__ __forceinline__ float tf32r(float x) {
    uint32_t y;
    asm("cvt.rna.tf32.f32 %0, %1;" : "=r"(y) : "f"(x));
    return __uint_as_float(y);
}
__device__ __forceinline__ void mma_tf32(float* c, const uint32_t* a, const uint32_t* b) {
    asm volatile(
        "mma.sync.aligned.m16n8k8.row.col.f32.tf32.tf32.f32 "
        "{%0,%1,%2,%3}, {%4,%5,%6,%7}, {%8,%9}, {%0,%1,%2,%3};"
        : "+f"(c[0]), "+f"(c[1]), "+f"(c[2]), "+f"(c[3])
        : "r"(a[0]), "r"(a[1]), "r"(a[2]), "r"(a[3]), "r"(b[0]), "r"(b[1]));
}
__device__ __forceinline__ void cp16(float* smem, const float* gmem) {
    uint32_t s = (uint32_t)__cvta_generic_to_shared(smem);
    asm volatile("cp.async.ca.shared.global [%0], [%1], 16;" :: "r"(s), "l"(gmem));
}

// ---------------- weight prep: tf32-round all 6 weights once ----------------
__global__ void prep_weights(const float* __restrict__ w0, const float* __restrict__ w1,
                             const float* __restrict__ w2, const float* __restrict__ w3,
                             const float* __restrict__ w4, const float* __restrict__ w5)
{
    int i = blockIdx.x * 256 + threadIdx.x;       // 0 .. 98303
    int w = i >> 14;
    int e = i & 16383;
    const float* src = (w == 0) ? w0 : (w == 1) ? w1 : (w == 2) ? w2
                     : (w == 3) ? w3 : (w == 4) ? w4 : w5;
    g_Wt[i] = tf32r(src[e]);
}

// ---------------- LayerNorm: one warp per row of 128; writes tf32-rounded ----------------
__global__ void ln_kernel(const float* __restrict__ in,
                          const float* __restrict__ scale,
                          const float* __restrict__ bias,
                          float* __restrict__ out)
{
    int warp = (blockIdx.x * blockDim.x + threadIdx.x) >> 5;
    int lane = threadIdx.x & 31;
    if (warp >= NROWS) return;
    const float4 v = *(const float4*)(in + (size_t)warp * CC + lane * 4);
    float s  = v.x + v.y + v.z + v.w;
    float sq = v.x*v.x + v.y*v.y + v.z*v.z + v.w*v.w;
    #pragma unroll
    for (int o = 16; o > 0; o >>= 1) {
        s  += __shfl_xor_sync(0xffffffffu, s,  o);
        sq += __shfl_xor_sync(0xffffffffu, sq, o);
    }
    float mean = s * (1.0f / CC);
    float var  = sq * (1.0f / CC) - mean * mean;
    float rstd = rsqrtf(var + 1e-5f);
    float4 sc = *(const float4*)(scale + lane * 4);
    float4 bi = *(const float4*)(bias  + lane * 4);
    float4 r;
    r.x = tf32r((v.x - mean) * rstd * sc.x + bi.x);
    r.y = tf32r((v.y - mean) * rstd * sc.y + bi.y);
    r.z = tf32r((v.z - mean) * rstd * sc.z + bi.z);
    r.w = tf32r((v.w - mean) * rstd * sc.w + bi.w);
    *(float4*)(out + (size_t)warp * CC + lane * 4) = r;
}

// ---------------- fused projections + gates + mask (+ fgate), einsum-style tiles ----------------
// grid (5, 2048), 128 threads, 4 warps (2m x 2n), warp tile 64 rows x 32 cols for BOTH W and Wg.
//   v 0..3: (sel = v>>1) x (half = v&1) -> (X@W+b)*mask*sigmoid(X@Wg+bg) -> g_Lt/g_Rt
//           (c-major, k-interleaved [0,4,1,5,2,6,3,7] per 8-group)
//   v 4   : fgate: W = cols 0-63, Wg = cols 64-127; sigmoid -> g_Fg (n-major)
__global__ void __launch_bounds__(128, 3) proj_lr(
    const float* __restrict__ b_l,  const float* __restrict__ b_lg,
    const float* __restrict__ b_r,  const float* __restrict__ b_rg,
    const float* __restrict__ b_fg,
    const float* __restrict__ mask)
{
    __shared__ __align__(16) float sbuf[2*2560 + 4*1152];   // 9728 floats; epilogue tile (8704) reuses
    float* Xs0  = sbuf;            // [2][128*20]
    float* Ws0  = sbuf + 5120;     // [2][16*72]
    float* Wgs0 = sbuf + 7424;     // [2][16*72]

    const int v = blockIdx.x;
    const float *W, *Wg, *B, *Bg;
    float* dstT = nullptr;
    if (v < 4) {
        int sel = v >> 1, half = v & 1;
        W  = g_Wt + (sel ? 2 : 0) * CC * CC + half * 64;
        Wg = g_Wt + (sel ? 3 : 1) * CC * CC + half * 64;
        B  = (sel ? b_r  : b_l)  + half * 64;
        Bg = (sel ? b_rg : b_lg) + half * 64;
        dstT = (sel ? g_Rt : g_Lt) + (size_t)(half * 64) * NROWS;
    } else {
        W  = g_Wt + 4 * CC * CC;
        Wg = g_Wt + 4 * CC * CC + 64;
        B  = b_fg;
        Bg = b_fg + 64;
    }

    const int n0   = blockIdx.y * 128;
    const int tid  = threadIdx.x;
    const int wid  = tid >> 5;
    const int lane = tid & 31;
    const int warp_m = wid >> 1;       // 0..1 (64 rows)
    const int warp_n = wid & 1;        // 0..1 (32 cols)
    const int lr = lane >> 2;
    const int lc = lane & 3;

    float acc[16][4], accg[16][4];
    #pragma unroll
    for (int t = 0; t < 16; t++)
        #pragma unroll
        for (int q = 0; q < 4; q++) { acc[t][q] = 0.0f; accg[t][q] = 0.0f; }

    // prefetch chunk 0 (X: 128 rows x 16 k = 512 float4; W/Wg: 16 x 64 = 256 float4 each)
    {
        #pragma unroll
        for (int u = 0; u < 4; u++) {
            int idx = tid + u * 128;
            int r = idx >> 2, q = idx & 3;
            cp16(&Xs0[r * 20 + q * 4], g_X + (size_t)(n0 + r) * CC + q * 4);
        }
        #pragma unroll
        for (int u = 0; u < 2; u++) {
            int idx = tid + u * 128;
            int k = idx >> 4, q = idx & 15;
            cp16(&Ws0[k * 72 + q * 4],  W  + (size_t)k * CC + q * 4);
            cp16(&Wgs0[k * 72 + q * 4], Wg + (size_t)k * CC + q * 4);
        }
        asm volatile("cp.async.commit_group;" ::: "memory");
    }

    for (int ch = 0; ch < 8; ch++) {
        asm volatile("cp.async.wait_group 0;" ::: "memory");
        __syncthreads();
        if (ch < 7) {
            int k0 = (ch + 1) * 16;
            int buf = (ch + 1) & 1;
            #pragma unroll
            for (int u = 0; u < 4; u++) {
                int idx = tid + u * 128;
                int r = idx >> 2, q = idx & 3;
                cp16(&Xs0[buf * 2560 + r * 20 + q * 4], g_X + (size_t)(n0 + r) * CC + k0 + q * 4);
            }
            #pragma unroll
            for (int u = 0; u < 2; u++) {
                int idx = tid + u * 128;
                int k = idx >> 4, q = idx & 15;
                cp16(&Ws0[buf * 1152 + k * 72 + q * 4],  W  + (size_t)(k0 + k) * CC + q * 4);
                cp16(&Wgs0[buf * 1152 + k * 72 + q * 4], Wg + (size_t)(k0 + k) * CC + q * 4);
            }
            asm volatile("cp.async.commit_group;" ::: "memory");
        }
        const float* Xs  = Xs0  + (ch & 1) * 2560;
        const float* Ws  = Ws0  + (ch & 1) * 1152;
        const float* Wgs = Wgs0 + (ch & 1) * 1152;
        #pragma unroll
        for (int ks = 0; ks < 16; ks += 8) {
            uint32_t a[4][4], b[4][2], bg[4][2];
            #pragma unroll
            for (int mt = 0; mt < 4; mt++) {
                int rb = (warp_m * 64 + mt * 16 + lr) * 20 + ks + lc;
                a[mt][0] = __float_as_uint(Xs[rb]);
                a[mt][1] = __float_as_uint(Xs[rb + 8 * 20]);
                a[mt][2] = __float_as_uint(Xs[rb + 4]);
                a[mt][3] = __float_as_uint(Xs[rb + 8 * 20 + 4]);
            }
            #pragma unroll
            for (int nt = 0; nt < 4; nt++) {
                int nb = warp_n * 32 + nt * 8 + lr;
                b[nt][0]  = __float_as_uint(Ws[(ks + lc) * 72 + nb]);
                b[nt][1]  = __float_as_uint(Ws[(ks + 4 + lc) * 72 + nb]);
                bg[nt][0] = __float_as_uint(Wgs[(ks + lc) * 72 + nb]);
                bg[nt][1] = __float_as_uint(Wgs[(ks + 4 + lc) * 72 + nb]);
            }
            #pragma unroll
            for (int mt = 0; mt < 4; mt++)
                #pragma unroll
                for (int nt = 0; nt < 4; nt++) {
                    mma_tf32(acc[mt * 4 + nt], a[mt], b[nt]);
                    mma_tf32(accg[mt * 4 + nt], a[mt], bg[nt]);
                }
        }
    }
    __syncthreads();

    if (v < 4) {
        // epilogue: gate+mask into 128x64 tile, then transposed c-major write (k-interleaved)
        float (*tile)[68] = (float (*)[68])sbuf;
        #pragma unroll
        for (int mt = 0; mt < 4; mt++) {
            #pragma unroll
            for (int nt = 0; nt < 4; nt++) {
                int col = warp_n * 32 + nt * 8 + lc * 2;
                float2 bb  = *(const float2*)(B + col);
                float2 bbg = *(const float2*)(Bg + col);
                #pragma unroll
                for (int h = 0; h < 2; h++) {
                    int rl = warp_m * 64 + mt * 16 + lr + h * 8;
                    int n = n0 + rl;
                    float pm = mask[n >> 9] * mask[n & 511];
                    float vx = (acc[mt * 4 + nt][h * 2 + 0] + bb.x) * pm
                             * sigf(accg[mt * 4 + nt][h * 2 + 0] + bbg.x);
                    float vy = (acc[mt * 4 + nt][h * 2 + 1] + bb.y) * pm
                             * sigf(accg[mt * 4 + nt][h * 2 + 1] + bbg.y);
                    tile[rl][col]     = tf32r(vx);
                    tile[rl][col + 1] = tf32r(vy);
                }
            }
        }
        __syncthreads();
        const int O8[8] = {0, 4, 1, 5, 2, 6, 3, 7};
        int c = tid >> 1;          // 0..63
        int h = tid & 1;           // 0..1, 64-row halves
        float* dst = dstT + (size_t)c * NROWS + n0 + h * 64;
        #pragma unroll
        for (int q = 0; q < 16; q++) {
            int g8 = (q >> 1) * 8;
            int e  = (q & 1) * 4;
            float4 vv;
            vv.x = tile[h * 64 + g8 + O8[e + 0]][c];
            vv.y = tile[h * 64 + g8 + O8[e + 1]][c];
            vv.z = tile[h * 64 + g8 + O8[e + 2]][c];
            vv.w = tile[h * 64 + g8 + O8[e + 3]][c];
            *(float4*)(dst + q * 4) = vv;
        }
    } else {
        // fgate epilogue: sigmoid, n-major; acc -> cols 0-63, accg -> cols 64-127
        #pragma unroll
        for (int mt = 0; mt < 4; mt++) {
            #pragma unroll
            for (int nt = 0; nt < 4; nt++) {
                int col = warp_n * 32 + nt * 8 + lc * 2;
                float2 bb  = *(const float2*)(B + col);
                float2 bbg = *(const float2*)(Bg + col);
                #pragma unroll
                for (int h = 0; h < 2; h++) {
                    int row = n0 + warp_m * 64 + mt * 16 + lr + h * 8;
                    float2 v0, v1;
                    v0.x = sigf(acc[mt * 4 + nt][h * 2 + 0] + bb.x);
                    v0.y = sigf(acc[mt * 4 + nt][h * 2 + 1] + bb.y);
                    v1.x = sigf(accg[mt * 4 + nt][h * 2 + 0] + bbg.x);
                    v1.y = sigf(accg[mt * 4 + nt][h * 2 + 1] + bbg.y);
                    *(float2*)(g_Fg + (size_t)row * CC + col)      = v0;
                    *(float2*)(g_Fg + (size_t)row * CC + col + 64) = v1;
                }
            }
        }
    }
}

// ---------------- einsum: cp.async double-buffered + k-interleaved LDS.64 fragments ----------------
__global__ void __launch_bounds__(128, 3) einsum_mma()
{
    __shared__ __align__(16) float As[2][128 * 24];
    __shared__ __align__(16) float Bs[2][128 * 24];
    const int c  = blockIdx.z;
    const int i0 = blockIdx.x * 128;
    const int j0 = blockIdx.y * 128;
    const int tid  = threadIdx.x;
    const int wid  = tid >> 5;
    const int lane = tid & 31;
    const int warp_m = wid >> 1;
    const int warp_n = wid & 1;
    const int lr = lane >> 2;
    const int lc = lane & 3;

    const float* Ap = g_Lt + (size_t)c * NROWS + (size_t)i0 * 512;
    const float* Bp = g_Rt + (size_t)c * NROWS + (size_t)j0 * 512;

    const int ldr0 = tid >> 2;
    const int ldq  = tid & 3;

    float acc[32][4];
    #pragma unroll
    for (int t = 0; t < 32; t++)
        #pragma unroll
        for (int q = 0; q < 4; q++) acc[t][q] = 0.0f;

    #pragma unroll
    for (int u = 0; u < 4; u++) {
        int r = ldr0 + u * 32;
        cp16(&As[0][r * 24 + ldq * 4], Ap + (size_t)r * 512 + ldq * 4);
        cp16(&Bs[0][r * 24 + ldq * 4], Bp + (size_t)r * 512 + ldq * 4);
    }
    asm volatile("cp.async.commit_group;" ::: "memory");

    for (int ch = 0; ch < 32; ch++) {
        asm volatile("cp.async.wait_group 0;" ::: "memory");
        __syncthreads();
        if (ch < 31) {
            int k1 = (ch + 1) * 16;
            int nb = (ch + 1) & 1;
            #pragma unroll
            for (int u = 0; u < 4; u++) {
                int r = ldr0 + u * 32;
                cp16(&As[nb][r * 24 + ldq * 4], Ap + (size_t)r * 512 + k1 + ldq * 4);
                cp16(&Bs[nb][r * 24 + ldq * 4], Bp + (size_t)r * 512 + k1 + ldq * 4);
            }
            asm volatile("cp.async.commit_group;" ::: "memory");
        }
        const float* A = As[ch & 1];
        const float* B = Bs[ch & 1];
        #pragma unroll
        for (int ks = 0; ks < 16; ks += 8) {
            uint32_t a[4][4], b[8][2];
            #pragma unroll
            for (int mt = 0; mt < 4; mt++) {
                int rb = (warp_m * 64 + mt * 16 + lr) * 24 + ks + 2 * lc;
                float2 p0 = *(const float2*)(&A[rb]);
                float2 p1 = *(const float2*)(&A[rb + 8 * 24]);
                a[mt][0] = __float_as_uint(p0.x);
                a[mt][1] = __float_as_uint(p1.x);
                a[mt][2] = __float_as_uint(p0.y);
                a[mt][3] = __float_as_uint(p1.y);
            }
            #pragma unroll
            for (int nt = 0; nt < 8; nt++) {
                int rb = (warp_n * 64 + nt * 8 + lr) * 24 + ks + 2 * lc;
                float2 pb = *(const float2*)(&B[rb]);
                b[nt][0] = __float_as_uint(pb.x);
                b[nt][1] = __float_as_uint(pb.y);
            }
            #pragma unroll
            for (int mt = 0; mt < 4; mt++)
                #pragma unroll
                for (int nt = 0; nt < 8; nt++)
                    mma_tf32(acc[mt * 8 + nt], a[mt], b[nt]);
        }
    }

    float* Op = g_Ot + (size_t)c * NROWS;
    #pragma unroll
    for (int mt = 0; mt < 4; mt++) {
        #pragma unroll
        for (int nt = 0; nt < 8; nt++) {
            int col = j0 + warp_n * 64 + nt * 8 + lc * 2;
            #pragma unroll
            for (int h = 0; h < 2; h++) {
                int row = i0 + warp_m * 64 + mt * 16 + lr + h * 8;
                float2 v;
                v.x = acc[mt * 8 + nt][h * 2 + 0];
                v.y = acc[mt * 8 + nt][h * 2 + 1];
                *(float2*)(Op + (size_t)row * 512 + col) = v;
            }
        }
    }
}

// ---------------- fused: Ot tile + in-place LN + GEMM(w_out) + gate ----------------
__global__ void __launch_bounds__(256) gemm_out_fused(
    const float* __restrict__ B,
    const float* __restrict__ fsc,
    const float* __restrict__ fbi,
    const float* __restrict__ gate,
    float* __restrict__ out)
{
    extern __shared__ float dsm[];
    float* tileA = dsm;                    // 128 c x 132 (16896)
    float* Ws0   = dsm + 16896;            // [2][16*136] (4352)
    float* s_mu  = Ws0 + 4352;             // 128
    float* s_rs  = s_mu + 128;             // 128
    float* s_sc  = s_rs + 128;             // 128 fsc
    float* s_bi  = s_sc + 128;             // 128 fbi
    const float* W = g_Wt + 5 * CC * CC;

    const int n0   = blockIdx.x * 128;
    const int tid  = threadIdx.x;
    const int wid  = tid >> 5;
    const int lane = tid & 31;
    const int warp_m = wid >> 2;
    const int warp_n = wid & 3;
    const int lr = lane >> 2;
    const int lc = lane & 3;

    if (tid < 128) { s_sc[tid] = fsc[tid]; }
    else           { s_bi[tid - 128] = fbi[tid - 128]; }
    #pragma unroll
    for (int u = 0; u < 16; u++) {
        int idx = tid + u * 256;
        int cc = idx >> 5;
        int q  = idx & 31;
        cp16(&tileA[cc * 132 + q * 4], g_Ot + (size_t)cc * NROWS + n0 + q * 4);
    }
    asm volatile("cp.async.commit_group;" ::: "memory");
    asm volatile("cp.async.wait_group 0;" ::: "memory");
    __syncthreads();

    #pragma unroll
    for (int rr = 0; rr < 16; rr++) {
        int r = wid * 16 + rr;
        float s = 0.0f, sq = 0.0f;
        #pragma unroll
        for (int m = 0; m < 4; m++) {
            float v = tileA[(lane + m * 32) * 132 + r];
            s += v; sq += v * v;
        }
        #pragma unroll
        for (int o = 16; o > 0; o >>= 1) {
            s  += __shfl_xor_sync(0xffffffffu, s,  o);
            sq += __shfl_xor_sync(0xffffffffu, sq, o);
        }
        if (lane == 0) {
            float mean = s * (1.0f / CC);
            s_mu[r] = mean;
            s_rs[r] = rsqrtf(sq * (1.0f / CC) - mean * mean + 1e-5f);
        }
    }
    __syncthreads();

    #pragma unroll
    for (int u = 0; u < 16; u++) {
        int idx = tid + u * 256;
        int cc = idx >> 5;
        int q  = idx & 31;
        float sc = s_sc[cc], bi = s_bi[cc];
        float4 vv = *(const float4*)(&tileA[cc * 132 + q * 4]);
        float4 m4 = *(const float4*)(&s_mu[q * 4]);
        float4 r4 = *(const float4*)(&s_rs[q * 4]);
        vv.x = tf32r((vv.x - m4.x) * r4.x * sc + bi);
        vv.y = tf32r((vv.y - m4.y) * r4.y * sc + bi);
        vv.z = tf32r((vv.z - m4.z) * r4.z * sc + bi);
        vv.w = tf32r((vv.w - m4.w) * r4.w * sc + bi);
        *(float4*)(&tileA[cc * 132 + q * 4]) = vv;
    }

    {
        #pragma unroll
        for (int u = 0; u < 2; u++) {
            int idx = tid + u * 256;
            int k = idx >> 5, q = idx & 31;
            cp16(&Ws0[k * 136 + q * 4], W + (size_t)k * CC + q * 4);
        }
        asm volatile("cp.async.commit_group;" ::: "memory");
    }

    float acc[16][4];
    #pragma unroll
    for (int t = 0; t < 16; t++)
        #pragma unroll
        for (int q = 0; q < 4; q++) acc[t][q] = 0.0f;

    for (int ch = 0; ch < 8; ch++) {
        asm volatile("cp.async.wait_group 0;" ::: "memory");
        __syncthreads();
        if (ch < 7) {
            int k0 = (ch + 1) * 16;
            int buf = (ch + 1) & 1;
            #pragma unroll
            for (int u = 0; u < 2; u++) {
                int idx = tid + u * 256;
                int k = idx >> 5, q = idx & 31;
                cp16(&Ws0[buf * 2176 + k * 136 + q * 4], W + (size_t)(k0 + k) * CC + q * 4);
            }
            asm volatile("cp.async.commit_group;" ::: "memory");
        }
        const float* Ws = Ws0 + (ch & 1) * 2176;
        const int kb = ch * 16;
        #pragma unroll
        for (int ks = 0; ks < 16; ks += 8) {
            uint32_t a[4][4], b[4][2];
            #pragma unroll
            for (int mt = 0; mt < 4; mt++) {
                int n = warp_m * 64 + mt * 16 + lr;
                int k = kb + ks + lc;
                a[mt][0] = __float_as_uint(tileA[k * 132 + n]);
                a[mt][1] = __float_as_uint(tileA[k * 132 + n + 8]);
                a[mt][2] = __float_as_uint(tileA[(k + 4) * 132 + n]);
                a[mt][3] = __float_as_uint(tileA[(k + 4) * 132 + n + 8]);
            }
            #pragma unroll
            for (int nt = 0; nt < 4; nt++) {
                int nb = warp_n * 32 + nt * 8 + lr;
                b[nt][0] = __float_as_uint(Ws[(ks + lc) * 136 + nb]);
                b[nt][1] = __float_as_uint(Ws[(ks + 4 + lc) * 136 + nb]);
            }
            #pragma unroll
            for (int mt = 0; mt < 4; mt++)
                #pragma unroll
                for (int nt = 0; nt < 4; nt++)
                    mma_tf32(acc[mt * 4 + nt], a[mt], b[nt]);
        }
    }

    #pragma unroll
    for (int mt = 0; mt < 4; mt++) {
        #pragma unroll
        for (int nt = 0; nt < 4; nt++) {
            int col = warp_n * 32 + nt * 8 + lc * 2;
            float2 bb = *(const float2*)(B + col);
            #pragma unroll
            for (int h = 0; h < 2; h++) {
                int row = n0 + warp_m * 64 + mt * 16 + lr + h * 8;
                float2 gv = *(const float2*)(gate + (size_t)row * CC + col);
                float2 v;
                v.x = (acc[mt * 4 + nt][h * 2 + 0] + bb.x) * gv.x;
                v.y = (acc[mt * 4 + nt][h * 2 + 1] + bb.y) * gv.y;
                *(float2*)(out + (size_t)row * CC + col) = v;
            }
        }
    }
}

// ---------------- host launch ----------------
extern "C" void kernel_launch(void* const* d_in, const int* in_sizes, int n_in,
                              void* d_out, int out_size)
{
    const float* act         = (const float*)d_in[0];
    const float* mask        = (const float*)d_in[1];
    const float* norm_scale  = (const float*)d_in[2];
    const float* norm_bias   = (const float*)d_in[3];
    const float* w_left      = (const float*)d_in[4];
    const float* b_left      = (const float*)d_in[5];
    const float* w_right     = (const float*)d_in[6];
    const float* b_right     = (const float*)d_in[7];
    const float* w_lgate     = (const float*)d_in[8];
    const float* b_lgate     = (const float*)d_in[9];
    const float* w_rgate     = (const float*)d_in[10];
    const float* b_rgate     = (const float*)d_in[11];
    const float* fnorm_scale = (const float*)d_in[12];
    const float* fnorm_bias  = (const float*)d_in[13];
    const float* w_out       = (const float*)d_in[14];
    const float* b_out       = (const float*)d_in[15];
    const float* w_fgate     = (const float*)d_in[16];
    const float* b_fgate     = (const float*)d_in[17];

    float *X, *Fg;
    cudaGetSymbolAddress((void**)&X,  g_X);
    cudaGetSymbolAddress((void**)&Fg, g_Fg);

    const int out_smem = (128 * 132 + 2 * 2176 + 4 * 128) * sizeof(float);
    static int attr_set = 0;
    if (!attr_set) {
        cudaFuncSetAttribute(gemm_out_fused,
                             cudaFuncAttributeMaxDynamicSharedMemorySize, out_smem);
        attr_set = 1;
    }

    // 0) tf32-round all weights once
    prep_weights<<<(6 * CC * CC) / 256, 256>>>(
        w_left, w_lgate, w_right, w_rgate, w_fgate, w_out);

    // 1) x = LN(act), tf32-rounded
    ln_kernel<<<NROWS / 8, 256>>>(act, norm_scale, norm_bias, X);

    // 2) fused projections + gates + mask + fgate -> Lt, Rt, Fg (pipelined, 128-thread blocks)
    proj_lr<<<dim3(5, NROWS / 128), 128>>>(
        b_left, b_lgate, b_right, b_rgate, b_fgate, mask);

    // 3) einsum on tensor cores -> Ot (c-major)
    einsum_mma<<<dim3(4, 4, CC), 128>>>();

    // 4) fused: in-place LN(Ot) + output projection + final gate
    gemm_out_fused<<<NROWS / 128, 256, out_smem>>>(
        b_out, fnorm_scale, fnorm_bias, Fg, (float*)d_out);
}